// round 15
// baseline (speedup 1.0000x reference)
#include <cuda_runtime.h>
#include <cuda_fp16.h>
#include <math.h>
#include <stdint.h>

// Problem: B=4, T=2048, D=2048, HEADS=16
// All-fp16 single-product chain (~5e-4 end-to-end):
//   K1: kvh = fp16(x @ w_qk^T)              merged, fp16 epilogue, ldc=4096
//   prep: kth = k0^T, vth = v^T (fp16 transposes; v used in-place from kvh)
//   K2: sh = fp16(scale * kth @ v^T)        B = kvh+2048 (ldb=4096)
//   K3: row softmax (fp16 in) -> ah fp16
//   K4: q = ah @ vth^T, scatter head-permuted fp16 rows -> qgh
//   K5: out = qgh @ wdh^T + bias (fp32)
// Engine R15: 128-thread CTAs, 4 warps (2x2), warp tile 64x64 (0.0625 B/MAC
// smem traffic, was 0.094), block 128x128, GBK=64, XOR-swizzled 128B rows,
// 3-stage cp.async ring, one __syncthreads per chunk, 2 CTAs/SM.

// ---------------------------------------------------------------- scratch ---
static __device__ __half g_kvh[33554432];   // 4*2048*4096 (k0 | v)
static __device__ __half g_sh [16777216];   // logits fp16
static __device__ __half g_xh [16777216];
static __device__ __half g_wqh[8388608];
static __device__ __half g_wdh[4194304];
static __device__ __half g_kth[16777216];   // k0^T
static __device__ __half g_vth[16777216];   // v^T
static __device__ __half g_ah [16777216];
static __device__ __half g_qgh[16777216];

// --------------------------------------------------------------- helpers ---
__device__ __forceinline__ uint32_t smem_u32(const void* p) {
    uint32_t a;
    asm("{ .reg .u64 t; cvta.to.shared.u64 t, %1; cvt.u32.u64 %0, t; }"
        : "=r"(a) : "l"(p));
    return a;
}
__device__ __forceinline__ void cp16(uint32_t dst, const void* src) {
    asm volatile("cp.async.cg.shared.global [%0], [%1], 16;"
                 :: "r"(dst), "l"(src) : "memory");
}
#define CP_COMMIT() asm volatile("cp.async.commit_group;" ::: "memory")

__device__ __forceinline__ void ldsm4(uint32_t* r, uint32_t addr) {
    asm volatile("ldmatrix.sync.aligned.m8n8.x4.shared.b16 {%0,%1,%2,%3}, [%4];"
                 : "=r"(r[0]), "=r"(r[1]), "=r"(r[2]), "=r"(r[3]) : "r"(addr));
}
__device__ __forceinline__ void mma16816(float* c, const uint32_t* a, const uint32_t* b) {
    asm volatile(
        "mma.sync.aligned.m16n8k16.row.col.f32.f16.f16.f32 "
        "{%0,%1,%2,%3}, {%4,%5,%6,%7}, {%8,%9}, {%0,%1,%2,%3};"
        : "+f"(c[0]), "+f"(c[1]), "+f"(c[2]), "+f"(c[3])
        : "r"(a[0]), "r"(a[1]), "r"(a[2]), "r"(a[3]), "r"(b[0]), "r"(b[1]));
}

// ----------------------------------------------------------- fp16 GEMM -----
// C(m,n) = alpha * sum_k A(m,k)*B(n,k) [+bias(n)]
// EPI 0: fp32 C (+bias). EPI 1: scatter fp16 rows r=(m&127)*64+z*16+(m>>7).
// EPI 2: fp16 C (alpha applied).
// K-major fp16 operands (row strides lda/ldb), K=2048. Block 128x128,
// 128 threads / 4 warps (2x2), warp tile 64x64, GBK=64, 3-ring, 2 CTAs/SM.
#define GK       2048
#define GBK      64
#define NCHUNK   (GK / GBK)        // 32
#define ROWB     128u              // 64 halves per row
#define TILE_B   (128u * ROWB)     // 16384
#define STAGE_B  (2u * TILE_B)     // 32768
#define GEMM_SMEM (3u * STAGE_B)   // 98304 -> 2 CTAs/SM
#define SSQ      4194304ull        // 2048*2048

template<int EPI>
__global__ __launch_bounds__(128, 2)
void gemm_f16(const __half* __restrict__ A, int lda, size_t strideA,
              const __half* __restrict__ B, int ldb, size_t strideB,
              float* __restrict__ C, __half* __restrict__ Ch,
              int ldc, size_t strideC,
              float alpha, const float* __restrict__ bias,
              __half* __restrict__ gh)
{
    extern __shared__ char smem[];
    const uint32_t sbase = smem_u32(smem);

    const int tid  = threadIdx.x;
    const int lane = tid & 31;
    const int wid  = tid >> 5;
    const int wm0  = (wid & 1) * 64;     // warp M offset
    const int wn0  = (wid >> 1) * 64;    // warp N offset

    A += blockIdx.z * strideA;
    B += blockIdx.z * strideB;
    if (EPI == 0) C  += blockIdx.z * strideC;
    if (EPI == 2) Ch += blockIdx.z * strideC;
    const int m0 = blockIdx.y * 128;
    const int n0 = blockIdx.x * 128;

    const int lc = tid & 7;    // 16B chunk in 128B row
    const int lr = tid >> 3;   // row 0..15 (x8 blocks)

    auto load_stage = [&](int t) {
        if (t < NCHUNK) {
            const uint32_t sb = sbase + (uint32_t)(t % 3) * STAGE_B;
            const int ks = t * GBK;
#pragma unroll
            for (int i = 0; i < 8; i++) {
                const uint32_t row = (uint32_t)(lr + i * 16);
                const uint32_t d = row * ROWB + (((uint32_t)lc ^ (row & 7u)) << 4);
                cp16(sb + d,          A + (size_t)(m0 + row) * lda + ks + lc * 8);
                cp16(sb + TILE_B + d, B + (size_t)(n0 + row) * ldb + ks + lc * 8);
            }
        }
        CP_COMMIT();
    };

    float acc[4][8][4];
#pragma unroll
    for (int i = 0; i < 4; i++)
#pragma unroll
        for (int j = 0; j < 8; j++)
#pragma unroll
            for (int k = 0; k < 4; k++) acc[i][j][k] = 0.f;

    const uint32_t a_row  = (uint32_t)(wm0 + (lane & 15));
    const uint32_t a_hi   = (uint32_t)(lane >> 4);
    const uint32_t a_sx   = a_row & 7u;
    const uint32_t a_base = a_row * ROWB;

    const uint32_t b_row  = (uint32_t)(wn0 + ((lane >> 4) & 1) * 8 + (lane & 7));
    const uint32_t b_hi   = (uint32_t)((lane >> 3) & 1);
    const uint32_t b_sx   = b_row & 7u;
    const uint32_t b_base = b_row * ROWB;

    load_stage(0);
    load_stage(1);

    for (int t = 0; t < NCHUNK; t++) {
        asm volatile("cp.async.wait_group 1;" ::: "memory");   // stage t landed
        __syncthreads();                                       // slot (t-1)%3 free
        load_stage(t + 2);

        const uint32_t sb = sbase + (uint32_t)(t % 3) * STAGE_B;
#pragma unroll
        for (int kk = 0; kk < 4; kk++) {
            const uint32_t ax = (((2u * kk + a_hi) ^ a_sx) << 4);
            const uint32_t bx = (((2u * kk + b_hi) ^ b_sx) << 4);
            uint32_t af[4][4], bf[4][4];
#pragma unroll
            for (int mt = 0; mt < 4; mt++)
                ldsm4(af[mt], sb + a_base + (uint32_t)mt * (16u * ROWB) + ax);
#pragma unroll
            for (int p = 0; p < 4; p++)
                ldsm4(bf[p], sb + TILE_B + b_base + (uint32_t)p * (16u * ROWB) + bx);
#pragma unroll
            for (int mt = 0; mt < 4; mt++)
#pragma unroll
                for (int p = 0; p < 4; p++) {
                    mma16816(acc[mt][2 * p + 0], af[mt], &bf[p][0]);
                    mma16816(acc[mt][2 * p + 1], af[mt], &bf[p][2]);
                }
        }
    }

    // ---- epilogue ----
    const int er = lane >> 2;
    const int ec = (lane & 3) * 2;
#pragma unroll
    for (int mt = 0; mt < 4; mt++)
#pragma unroll
        for (int nt = 0; nt < 8; nt++) {
            int m = m0 + wm0 + mt * 16 + er;
            int n = n0 + wn0 + nt * 8 + ec;
            if (EPI == 0) {
                float b0 = 0.f, b1 = 0.f;
                if (bias) { b0 = __ldg(bias + n); b1 = __ldg(bias + n + 1); }
                float2 v0, v1;
                v0.x = alpha * acc[mt][nt][0] + b0;
                v0.y = alpha * acc[mt][nt][1] + b1;
                v1.x = alpha * acc[mt][nt][2] + b0;
                v1.y = alpha * acc[mt][nt][3] + b1;
                *(float2*)&C[(size_t)m * (size_t)ldc + n]       = v0;
                *(float2*)&C[(size_t)(m + 8) * (size_t)ldc + n] = v1;
            } else if (EPI == 1) {
                const int b = (int)blockIdx.z;
                int r1 = ((m & 127) << 6) + b * 16 + (m >> 7);
                int m2 = m + 8;
                int r2 = ((m2 & 127) << 6) + b * 16 + (m2 >> 7);
                *(__half2*)(gh + (size_t)r1 * 2048 + n) =
                    __halves2half2(__float2half(acc[mt][nt][0]),
                                   __float2half(acc[mt][nt][1]));
                *(__half2*)(gh + (size_t)r2 * 2048 + n) =
                    __halves2half2(__float2half(acc[mt][nt][2]),
                                   __float2half(acc[mt][nt][3]));
            } else {
                *(__half2*)(Ch + (size_t)m * (size_t)ldc + n) =
                    __halves2half2(__float2half(alpha * acc[mt][nt][0]),
                                   __float2half(alpha * acc[mt][nt][1]));
                *(__half2*)(Ch + (size_t)(m + 8) * (size_t)ldc + n) =
                    __halves2half2(__float2half(alpha * acc[mt][nt][2]),
                                   __float2half(alpha * acc[mt][nt][3]));
            }
        }
}

// ----------------------------------------------------------- prep kernels ---
// fp32 [rows x 2048] -> fp16
__global__ __launch_bounds__(256)
void copy_conv(const float* __restrict__ src, __half* __restrict__ dst)
{
    size_t row = blockIdx.y;
    size_t col = (size_t)blockIdx.x * 1024 + threadIdx.x * 4;
    float4 v = *(const float4*)(src + row * 2048 + col);
    size_t o = row * 2048 + col;
    ((__half2*)(dst + o))[0] = __halves2half2(__float2half(v.x), __float2half(v.y));
    ((__half2*)(dst + o))[1] = __halves2half2(__float2half(v.z), __float2half(v.w));
}

// fp16 transpose: dst[i][m] = src[m][i], 2048x2048 per batch, 64x64 tiles
__global__ __launch_bounds__(256)
void transpose_h(const __half* __restrict__ src, int src_ld, size_t src_bstride,
                 __half* __restrict__ dst, size_t dst_bstride)
{
    __shared__ __half tile[64][65];
    const int tid = threadIdx.x;
    const int cp  = tid & 31;
    const int r0  = tid >> 5;
    const int m0 = blockIdx.y * 64, i0 = blockIdx.x * 64;
    const __half* s = src + blockIdx.z * src_bstride;
#pragma unroll
    for (int i = 0; i < 8; i++) {
        int row = r0 + i * 8;
        __half2 v = *(const __half2*)(s + (size_t)(m0 + row) * src_ld + i0 + 2 * cp);
        tile[row][2 * cp]     = __low2half(v);
        tile[row][2 * cp + 1] = __high2half(v);
    }
    __syncthreads();
    __half* d = dst + blockIdx.z * dst_bstride;
#pragma unroll
    for (int i = 0; i < 8; i++) {
        int irow = r0 + i * 8;
        __half2 v = __halves2half2(tile[2 * cp][irow], tile[2 * cp + 1][irow]);
        *(__half2*)(d + (size_t)(i0 + irow) * 2048 + m0 + 2 * cp) = v;
    }
}

// Row softmax, fp16 in -> fp16 out, 2048 cols, 256 threads x 8 elems.
__global__ __launch_bounds__(256)
void softmax_h(const __half* __restrict__ s, __half* __restrict__ a)
{
    const __half* p = s + (size_t)blockIdx.x * 2048;
    int tid = threadIdx.x, warp = tid >> 5, lane = tid & 31;
    __shared__ float red[8];

    __half hv[8];
    *(uint4*)hv = *(const uint4*)(p + tid * 8);
    float f[8];
#pragma unroll
    for (int i = 0; i < 8; i++) f[i] = __half2float(hv[i]);

    float m = f[0];
#pragma unroll
    for (int i = 1; i < 8; i++) m = fmaxf(m, f[i]);
#pragma unroll
    for (int o = 16; o > 0; o >>= 1) m = fmaxf(m, __shfl_xor_sync(0xffffffffu, m, o));
    if (lane == 0) red[warp] = m;
    __syncthreads();
    float bm = red[0];
#pragma unroll
    for (int i = 1; i < 8; i++) bm = fmaxf(bm, red[i]);
    __syncthreads();

    float sm = 0.f;
#pragma unroll
    for (int i = 0; i < 8; i++) { f[i] = __expf(f[i] - bm); sm += f[i]; }
#pragma unroll
    for (int o = 16; o > 0; o >>= 1) sm += __shfl_xor_sync(0xffffffffu, sm, o);
    if (lane == 0) red[warp] = sm;
    __syncthreads();
    float tot = red[0];
#pragma unroll
    for (int i = 1; i < 8; i++) tot += red[i];
    float inv = 1.f / tot;

    __half2 o2[4];
#pragma unroll
    for (int i = 0; i < 4; i++)
        o2[i] = __halves2half2(__float2half(f[2 * i] * inv),
                               __float2half(f[2 * i + 1] * inv));
    *(uint4*)(a + (size_t)blockIdx.x * 2048 + tid * 8) = *(uint4*)o2;
}

// ------------------------------------------------------------------ driver ---
extern "C" void kernel_launch(void* const* d_in, const int* in_sizes, int n_in,
                              void* d_out, int out_size)
{
    const float* x       = (const float*)d_in[0];
    const float* w_qk    = (const float*)d_in[1];
    const float* w_dense = (const float*)d_in[2];
    const float* b_dense = (const float*)d_in[3];
    float* out = (float*)d_out;

    __half *kvh, *sh, *xh, *wqh, *wdh, *kth, *vth, *ah, *qgh;
    cudaGetSymbolAddress((void**)&kvh, g_kvh);
    cudaGetSymbolAddress((void**)&sh,  g_sh);
    cudaGetSymbolAddress((void**)&xh,  g_xh);
    cudaGetSymbolAddress((void**)&wqh, g_wqh);
    cudaGetSymbolAddress((void**)&wdh, g_wdh);
    cudaGetSymbolAddress((void**)&kth, g_kth);
    cudaGetSymbolAddress((void**)&vth, g_vth);
    cudaGetSymbolAddress((void**)&ah,  g_ah);
    cudaGetSymbolAddress((void**)&qgh, g_qgh);

    cudaFuncSetAttribute(gemm_f16<0>, cudaFuncAttributeMaxDynamicSharedMemorySize, GEMM_SMEM);
    cudaFuncSetAttribute(gemm_f16<1>, cudaFuncAttributeMaxDynamicSharedMemorySize, GEMM_SMEM);
    cudaFuncSetAttribute(gemm_f16<2>, cudaFuncAttributeMaxDynamicSharedMemorySize, GEMM_SMEM);

    const float scale = (float)(1.0 / sqrt(2048.0 * 2047.0 / 2.0));
    const size_t sKV = 2048ull * 4096ull;

    // fp16 conversions of inputs
    copy_conv<<<dim3(2, 8192, 1), 256>>>(x,       xh);
    copy_conv<<<dim3(2, 4096, 1), 256>>>(w_qk,    wqh);
    copy_conv<<<dim3(2, 2048, 1), 256>>>(w_dense, wdh);

    // K1: kvh = fp16(x @ w_qk^T)   M=8192 N=4096, fp16 epilogue
    gemm_f16<2><<<dim3(32, 64, 1), 128, GEMM_SMEM>>>(
        xh, 2048, 0, wqh, 2048, 0, nullptr, kvh, 4096, 0, 1.f, nullptr, nullptr);

    // preps: kth = k0^T, vth = v^T (fp16 transposes; v used in-place for K2)
    transpose_h<<<dim3(32, 32, 4), 256>>>(kvh,        4096, sKV, kth, SSQ);
    transpose_h<<<dim3(32, 32, 4), 256>>>(kvh + 2048, 4096, sKV, vth, SSQ);

    // K2: sh = fp16(scale * kth @ v^T)   B = v half of kvh, ldb=4096
    gemm_f16<2><<<dim3(16, 16, 4), 128, GEMM_SMEM>>>(
        kth, 2048, SSQ, kvh + 2048, 4096, sKV, nullptr, sh, 2048, SSQ,
        scale, nullptr, nullptr);

    // K3: softmax -> fp16 a
    softmax_h<<<8192, 256>>>(sh, ah);

    // K4: q = a @ vt^T; scatter head-permuted fp16 rows
    gemm_f16<1><<<dim3(16, 16, 4), 128, GEMM_SMEM>>>(
        ah, 2048, SSQ, vth, 2048, SSQ, nullptr, nullptr, 0, 0, 1.f, nullptr, qgh);

    // K5: out = qg @ w_dense^T + bias
    gemm_f16<0><<<dim3(16, 64, 1), 128, GEMM_SMEM>>>(
        qgh, 2048, 0, wdh, 2048, 0, out, nullptr, 2048, 0, 1.f, b_dense, nullptr);
}